// round 17
// baseline (speedup 1.0000x reference)
#include <cuda_runtime.h>
#include <cuda_bf16.h>
#include <math.h>
#include <stdint.h>

// ============================================================================
// pairwise |x_i - x_j| -> 4x(1x1conv + BN(train) + LeakyReLU) -> linear
// -> softmax(axis=2) -> top-K scatter mask.
// Symmetry: logits[b,i,j]==logits[b,j,i] -> compute upper triangle only.
// GEMMs via mma.sync bf16, bf16x2 split (AhBh + AhBl + AlBh, fp32 accum).
// R9: 64x64 warp tiles (4 warps/CTA) to cut ldmatrix traffic per MAC;
//     BN finalize folded into GEMM prologue (kills 4 tiny launches).
// ============================================================================

namespace cfg {
constexpr int B = 8, V = 201, D = 256, H = 128;
constexpr int T = V * (V + 1) / 2;     // 20301
constexpr int NTRI = B * T;            // 162408
constexpr int NFULL = B * V * V;       // 323208 (BN statistics population)
constexpr int KTOP = 100;
constexpr float EPS = 1e-5f;
constexpr float SLOPE = 0.01f;
constexpr int MT = (NTRI + 127) / 128; // 1269 row tiles
}

// Scratch (static device globals -- no allocations allowed)
__device__ float  g_bufA[(size_t)cfg::NTRI * 256];
__device__ float  g_bufB[(size_t)cfg::NTRI * 256];
__device__ float  g_logits[cfg::NTRI];
__device__ double g_sum[4][256];
__device__ double g_sumsq[4][256];
__device__ int2   g_tri[cfg::T];
// split weights: L0 @0 (65536), L1 @65536, L2 @131072 (32768), L3 @163840 (16384)
__device__ __nv_bfloat16 g_whi[180224];
__device__ __nv_bfloat16 g_wlo[180224];

__device__ __forceinline__ float lrelu(float v) {
    return v >= 0.f ? v : cfg::SLOPE * v;
}

__device__ __forceinline__ uint32_t smem_u32(const void* p) {
    uint32_t a;
    asm("{ .reg .u64 t; cvta.to.shared.u64 t, %1; cvt.u32.u64 %0, t; }"
        : "=r"(a) : "l"(p));
    return a;
}

__device__ __forceinline__ void ldmx4(uint32_t* r, uint32_t addr) {
    asm volatile("ldmatrix.sync.aligned.m8n8.x4.shared.b16 {%0,%1,%2,%3}, [%4];"
        : "=r"(r[0]), "=r"(r[1]), "=r"(r[2]), "=r"(r[3]) : "r"(addr));
}

__device__ __forceinline__ void mma16816(float* c, const uint32_t* a,
                                         const uint32_t* b) {
    asm volatile(
        "mma.sync.aligned.m16n8k16.row.col.f32.bf16.bf16.f32 "
        "{%0,%1,%2,%3}, {%4,%5,%6,%7}, {%8,%9}, {%0,%1,%2,%3};"
        : "+f"(c[0]), "+f"(c[1]), "+f"(c[2]), "+f"(c[3])
        : "r"(a[0]), "r"(a[1]), "r"(a[2]), "r"(a[3]), "r"(b[0]), "r"(b[1]));
}

__device__ __forceinline__ uint32_t packsplit(float a, float b, uint32_t* lo) {
    __nv_bfloat16 ha = __float2bfloat16(a), hb = __float2bfloat16(b);
    __nv_bfloat16 la = __float2bfloat16(a - __bfloat162float(ha));
    __nv_bfloat16 lb = __float2bfloat16(b - __bfloat162float(hb));
    *lo = (uint32_t)__bfloat16_as_ushort(la) | ((uint32_t)__bfloat16_as_ushort(lb) << 16);
    return (uint32_t)__bfloat16_as_ushort(ha) | ((uint32_t)__bfloat16_as_ushort(hb) << 16);
}

// ---------------------------------------------------------------------------
__global__ void k_init() {
    int t = blockIdx.x * blockDim.x + threadIdx.x;
    if (t < 1024) { ((double*)g_sum)[t] = 0.0; ((double*)g_sumsq)[t] = 0.0; }
}

__global__ void k_tri() {
    int i = blockIdx.x;
    int base = i * cfg::V - (i * (i - 1)) / 2;
    for (int j = i + threadIdx.x; j < cfg::V; j += blockDim.x)
        g_tri[base + (j - i)] = make_int2(i, j);
}

// Pre-split all layer weights into bf16 hi/lo planes.
__global__ void k_wsplit(const float* __restrict__ w0, const float* __restrict__ w1,
                         const float* __restrict__ w2, const float* __restrict__ w3) {
    int t = blockIdx.x * blockDim.x + threadIdx.x;
    const float* src; int off, idx;
    if      (t < 65536)  { src = w0; off = 0;      idx = t; }
    else if (t < 131072) { src = w1; off = 65536;  idx = t - 65536; }
    else if (t < 163840) { src = w2; off = 131072; idx = t - 131072; }
    else if (t < 180224) { src = w3; off = 163840; idx = t - 163840; }
    else return;
    float v = src[idx];
    __nv_bfloat16 h = __float2bfloat16(v);
    g_whi[off + idx] = h;
    g_wlo[off + idx] = __float2bfloat16(v - __bfloat162float(h));
}

// ---------------------------------------------------------------------------
// mma.sync fused GEMM layer. CTA tile 128x128; 4 warps (2x2), warp tile 64x64.
// K chunks of 32. bf16 hi/lo split, 3 mma terms. Prev-layer BN scale/shift
// computed in-kernel from g_sum (MODE 1); MODE 0: A = |x_i - x_j|.
// Epilogue: +bias, fp32 store, weighted BN stats (diag w=1, offdiag w=2).
// SMEM rows padded to 40 bf16 (80 B): ldmatrix conflict-free.
// ---------------------------------------------------------------------------
template<int CIN, int COUT, int MODE>
__global__ void __launch_bounds__(128, 2)
k_mma(const float* __restrict__ in,
      const __nv_bfloat16* __restrict__ whi, const __nv_bfloat16* __restrict__ wlo,
      const float* __restrict__ bias,
      const double* __restrict__ psum, const double* __restrict__ psumsq,
      const float* __restrict__ gamma, const float* __restrict__ beta,
      float* __restrict__ out, double* __restrict__ osum, double* __restrict__ osumsq)
{
    using namespace cfg;
    __shared__ __align__(16) uint16_t sAh[128 * 40];
    __shared__ __align__(16) uint16_t sAl[128 * 40];
    __shared__ __align__(16) uint16_t sBh[128 * 40];
    __shared__ __align__(16) uint16_t sBl[128 * 40];
    __shared__ float wrow[128];
    __shared__ __align__(16) float s_scale[CIN];
    __shared__ __align__(16) float s_shift[CIN];

    const int tid = threadIdx.x, lane = tid & 31, wid = tid >> 5;
    const int row0 = blockIdx.x * 128, n0 = blockIdx.y * 128;
    const int wy = wid & 1, wx = wid >> 1;          // 2x2 warp grid

    // prev-layer BN fold (MODE 1): scale/shift from global sums
    if (MODE == 1) {
        #pragma unroll
        for (int c = tid; c < CIN; c += 128) {
            double m = psum[c] / (double)NFULL;
            double vr = psumsq[c] / (double)NFULL - m * m;
            float s = gamma[c] / sqrtf((float)vr + EPS);
            s_scale[c] = s;
            s_shift[c] = beta[c] - (float)m * s;
        }
    }
    {   // row weights for BN stats (0 = padding row)
        int r = row0 + tid; float w = 0.f;
        if (r < NTRI) { int b = r / T; int2 ij = g_tri[r - b * T];
                        w = (ij.x == ij.y) ? 1.f : 2.f; }
        wrow[tid] = w;
    }

    // producer: thread t owns A row t and B row t of the CTA tile
    int gr = row0 + tid; if (gr >= NTRI) gr = NTRI - 1;   // clamp (w=0 in stats)
    const float *pa0, *pa1 = nullptr;
    if (MODE == 0) {
        int b = gr / T; int2 ij = g_tri[gr - b * T];
        pa0 = in + (size_t)(b * V + ij.x) * D;
        pa1 = in + (size_t)(b * V + ij.y) * D;
    } else {
        pa0 = in + (size_t)gr * CIN;
    }
    const __nv_bfloat16* pwh = whi + (size_t)(n0 + tid) * CIN;
    const __nv_bfloat16* pwl = wlo + (size_t)(n0 + tid) * CIN;

    // ldmatrix lane addressing (conflict-free with 80 B row stride)
    const int adr = lane & 15, adk = (lane >> 4) * 8;                 // A: m,k
    const int bdn = (lane & 7) + ((lane & 16) ? 8 : 0);               // B: n
    const int bdk = (lane & 8) ? 8 : 0;                               // B: k
    const uint32_t aHb = smem_u32(&sAh[(wy * 64 + adr) * 40 + adk]);
    const uint32_t aLb = smem_u32(&sAl[(wy * 64 + adr) * 40 + adk]);
    const uint32_t bHb = smem_u32(&sBh[(wx * 64 + bdn) * 40 + bdk]);
    const uint32_t bLb = smem_u32(&sBl[(wx * 64 + bdn) * 40 + bdk]);

    float acc[4][8][4];
    #pragma unroll
    for (int m = 0; m < 4; ++m)
        #pragma unroll
        for (int n = 0; n < 8; ++n)
            #pragma unroll
            for (int q = 0; q < 4; ++q) acc[m][n][q] = 0.f;

    constexpr int NCH = CIN / 32;
    for (int c = 0; c < NCH; ++c) {
        const int k0 = c * 32;
        __syncthreads();   // prev chunk consumed (also orders bn table / wrow)

        // ---- produce: convert one A row + copy one B row (32 k-values) ----
        uint32_t hi[16], lo[16];
        #pragma unroll
        for (int q = 0; q < 8; ++q) {
            float4 u = *(const float4*)(pa0 + k0 + q * 4);
            float v0, v1, v2, v3;
            if (MODE == 0) {
                float4 z = *(const float4*)(pa1 + k0 + q * 4);
                v0 = fabsf(u.x - z.x); v1 = fabsf(u.y - z.y);
                v2 = fabsf(u.z - z.z); v3 = fabsf(u.w - z.w);
            } else {
                float4 sc = *(const float4*)&s_scale[k0 + q * 4];
                float4 sh = *(const float4*)&s_shift[k0 + q * 4];
                v0 = lrelu(fmaf(u.x, sc.x, sh.x));
                v1 = lrelu(fmaf(u.y, sc.y, sh.y));
                v2 = lrelu(fmaf(u.z, sc.z, sh.z));
                v3 = lrelu(fmaf(u.w, sc.w, sh.w));
            }
            hi[2 * q]     = packsplit(v0, v1, &lo[2 * q]);
            hi[2 * q + 1] = packsplit(v2, v3, &lo[2 * q + 1]);
        }
        #pragma unroll
        for (int q = 0; q < 4; ++q) {
            *(uint4*)&sAh[tid * 40 + q * 8] =
                make_uint4(hi[4*q], hi[4*q+1], hi[4*q+2], hi[4*q+3]);
            *(uint4*)&sAl[tid * 40 + q * 8] =
                make_uint4(lo[4*q], lo[4*q+1], lo[4*q+2], lo[4*q+3]);
            *(uint4*)&sBh[tid * 40 + q * 8] = ((const uint4*)(pwh + k0))[q];
            *(uint4*)&sBl[tid * 40 + q * 8] = ((const uint4*)(pwl + k0))[q];
        }
        __syncthreads();

        // ---- consume: 64x64 warp tile, 2 k-steps of 16 ----
        #pragma unroll
        for (int ks = 0; ks < 2; ++ks) {
            uint32_t bh[4][4], bl[4][4];
            #pragma unroll
            for (int np = 0; np < 4; ++np) {
                ldmx4(bh[np], bHb + np * 16 * 80 + ks * 32);
                ldmx4(bl[np], bLb + np * 16 * 80 + ks * 32);
            }
            #pragma unroll
            for (int mt = 0; mt < 4; ++mt) {
                uint32_t ah[4], al[4];
                ldmx4(ah, aHb + mt * 16 * 80 + ks * 32);
                ldmx4(al, aLb + mt * 16 * 80 + ks * 32);
                #pragma unroll
                for (int nt = 0; nt < 8; ++nt) {
                    const uint32_t* ph = &bh[nt >> 1][(nt & 1) * 2];
                    const uint32_t* pl = &bl[nt >> 1][(nt & 1) * 2];
                    mma16816(acc[mt][nt], ah, ph);
                    mma16816(acc[mt][nt], ah, pl);
                    mma16816(acc[mt][nt], al, ph);
                }
            }
        }
    }

    // ---------------- epilogue ----------------
    float ps[16], ps2[16];
    #pragma unroll
    for (int j = 0; j < 16; ++j) { ps[j] = 0.f; ps2[j] = 0.f; }

    #pragma unroll
    for (int nt = 0; nt < 8; ++nt) {
        const int col = n0 + wx * 64 + nt * 8 + (lane & 3) * 2;
        const float b0 = bias[col], b1 = bias[col + 1];
        #pragma unroll
        for (int mt = 0; mt < 4; ++mt) {
            const int lr = wy * 64 + mt * 16 + (lane >> 2);
            const int r1 = row0 + lr, r2 = r1 + 8;
            const float w1 = wrow[lr], w2 = wrow[lr + 8];
            float y0 = acc[mt][nt][0] + b0, y1 = acc[mt][nt][1] + b1;
            float y2 = acc[mt][nt][2] + b0, y3 = acc[mt][nt][3] + b1;
            if (r1 < NTRI) { float2 o = make_float2(y0, y1);
                *(float2*)(out + (size_t)r1 * COUT + col) = o; }
            if (r2 < NTRI) { float2 o = make_float2(y2, y3);
                *(float2*)(out + (size_t)r2 * COUT + col) = o; }
            ps[nt * 2]      += w1 * y0 + w2 * y2;
            ps[nt * 2 + 1]  += w1 * y1 + w2 * y3;
            ps2[nt * 2]     += w1 * y0 * y0 + w2 * y2 * y2;
            ps2[nt * 2 + 1] += w1 * y1 * y1 + w2 * y3 * y3;
        }
    }
    #pragma unroll
    for (int off = 4; off <= 16; off <<= 1)
        #pragma unroll
        for (int j = 0; j < 16; ++j) {
            ps[j]  += __shfl_xor_sync(0xffffffffu, ps[j],  off);
            ps2[j] += __shfl_xor_sync(0xffffffffu, ps2[j], off);
        }
    if (lane < 4) {
        #pragma unroll
        for (int nt = 0; nt < 8; ++nt) {
            const int col = n0 + wx * 64 + nt * 8 + lane * 2;
            atomicAdd(&osum[col],       (double)ps[nt * 2]);
            atomicAdd(&osum[col + 1],   (double)ps[nt * 2 + 1]);
            atomicAdd(&osumsq[col],     (double)ps2[nt * 2]);
            atomicAdd(&osumsq[col + 1], (double)ps2[nt * 2 + 1]);
        }
    }
}

// ---------------------------------------------------------------------------
// logits[r] = dot(leaky(bn3(y3[r,:])), w4) + b4. One warp per row.
// BN3 scale/shift computed in-block from g_sum[3].
__global__ void k_final(const float* __restrict__ y, const float* __restrict__ w4,
                        const float* __restrict__ b4,
                        const float* __restrict__ gm, const float* __restrict__ be) {
    using namespace cfg;
    __shared__ __align__(16) float s4[H];
    __shared__ __align__(16) float h4[H];
    int tid = threadIdx.x;
    if (tid < H) {
        double m = g_sum[3][tid] / (double)NFULL;
        double vr = g_sumsq[3][tid] / (double)NFULL - m * m;
        float s = gm[tid] / sqrtf((float)vr + EPS);
        s4[tid] = s;
        h4[tid] = be[tid] - (float)m * s;
    }
    __syncthreads();

    int warp = tid >> 5, lane = tid & 31;
    int r = blockIdx.x * 8 + warp;
    if (r >= NTRI) return;
    int c = lane * 4;
    float4 u = *(const float4*)(y + (size_t)r * H + c);
    float4 s = *(const float4*)&s4[c];
    float4 h = *(const float4*)&h4[c];
    float4 w = *(const float4*)(w4 + c);
    float d = lrelu(fmaf(u.x, s.x, h.x)) * w.x
            + lrelu(fmaf(u.y, s.y, h.y)) * w.y
            + lrelu(fmaf(u.z, s.z, h.z)) * w.z
            + lrelu(fmaf(u.w, s.w, h.w)) * w.w;
    #pragma unroll
    for (int o = 16; o > 0; o >>= 1) d += __shfl_xor_sync(0xffffffffu, d, o);
    if (lane == 0) g_logits[r] = d + b4[0];
}

// softmax over j + stable top-K mask (rank by counting, matches jax tie-break)
__global__ void k_softmax(float* __restrict__ outp) {
    using namespace cfg;
    __shared__ float Av[256];
    __shared__ float red[256];
    int b = blockIdx.x / V;
    int i = blockIdx.x - b * V;
    int tid = threadIdx.x;

    float v = -INFINITY;
    if (tid < V) {
        int j  = tid;
        int i2 = i < j ? i : j;
        int j2 = i < j ? j : i;
        int t  = i2 * V - (i2 * (i2 - 1)) / 2 + (j2 - i2);
        v = g_logits[b * T + t];
    }
    red[tid] = v;
    __syncthreads();
    for (int o = 128; o > 0; o >>= 1) {
        if (tid < o) red[tid] = fmaxf(red[tid], red[tid + o]);
        __syncthreads();
    }
    float mx = red[0];
    __syncthreads();

    float e = (tid < V) ? expf(v - mx) : 0.f;
    Av[tid]  = e;
    red[tid] = e;
    __syncthreads();
    for (int o = 128; o > 0; o >>= 1) {
        if (tid < o) red[tid] += red[tid + o];
        __syncthreads();
    }
    float inv = 1.f / red[0];

    if (tid < V) {
        float ej = Av[tid];
        int rank = 0;
        for (int l = 0; l < V; ++l) {
            float el = Av[l];
            rank += (el > ej) || (el == ej && l < tid);
        }
        outp[(size_t)(b * V + i) * V + tid] = (rank < KTOP) ? ej * inv : 0.f;
    }
}

// ---------------------------------------------------------------------------
extern "C" void kernel_launch(void* const* d_in, const int* in_sizes, int n_in,
                              void* d_out, int out_size) {
    using namespace cfg;
    const float* x = (const float*)d_in[0];
    const float* w[4]; const float* bb[4]; const float* gm[4]; const float* be[4];
    for (int i = 0; i < 4; ++i) {
        w[i]  = (const float*)d_in[1 + 4 * i];
        bb[i] = (const float*)d_in[2 + 4 * i];
        gm[i] = (const float*)d_in[3 + 4 * i];
        be[i] = (const float*)d_in[4 + 4 * i];
    }
    const float* w4 = (const float*)d_in[17];
    const float* b4 = (const float*)d_in[18];
    float* out = (float*)d_out;

    float *bufA, *bufB;
    double *sum, *sumsq;
    __nv_bfloat16 *whi, *wlo;
    cudaGetSymbolAddress((void**)&bufA, g_bufA);
    cudaGetSymbolAddress((void**)&bufB, g_bufB);
    cudaGetSymbolAddress((void**)&sum,  g_sum);
    cudaGetSymbolAddress((void**)&sumsq, g_sumsq);
    cudaGetSymbolAddress((void**)&whi,  g_whi);
    cudaGetSymbolAddress((void**)&wlo,  g_wlo);

    k_init<<<1, 1024>>>();
    k_tri<<<V, 256>>>();
    k_wsplit<<<704, 256>>>(w[0], w[1], w[2], w[3]);

    k_mma<256, 256, 0><<<dim3(MT, 2), 128>>>(
        x, whi, wlo, bb[0], nullptr, nullptr, nullptr, nullptr,
        bufA, sum, sumsq);

    k_mma<256, 256, 1><<<dim3(MT, 2), 128>>>(
        bufA, whi + 65536, wlo + 65536, bb[1], sum, sumsq, gm[0], be[0],
        bufB, sum + 256, sumsq + 256);

    k_mma<256, 128, 1><<<dim3(MT, 1), 128>>>(
        bufB, whi + 131072, wlo + 131072, bb[2], sum + 256, sumsq + 256, gm[1], be[1],
        bufA, sum + 512, sumsq + 512);

    k_mma<128, 128, 1><<<dim3(MT, 1), 128>>>(
        bufA, whi + 163840, wlo + 163840, bb[3], sum + 512, sumsq + 512, gm[2], be[2],
        bufB, sum + 768, sumsq + 768);

    k_final<<<NTRI / 8, 256>>>(bufB, w4, b4, gm[3], be[3]);
    k_softmax<<<B * V, 256>>>(out);
}